// round 10
// baseline (speedup 1.0000x reference)
#include <cuda_runtime.h>
#include <cuda_fp16.h>
#include <stdint.h>

#define H       1024
#define I_DIM   256
#define O_DIM   128
#define BATCH   64
#define T_STEPS 512
#define NTOT    2176      // H + H + O
#define KAUG    3072      // 3*H
#define KX      768       // 3*I
#define MX      32768     // BATCH*T
#define ALPHA   0.1f

#define NTILES  34        // 2176/64
#define KCHUNK  4         // K split: 4 x 768
#define NCTA    136       // NTILES*KCHUNK
#define NTHR    512       // 2 teams x 256
#define TB      32        // batches per team

#define SW_PITCH 776      // halfs per W row in smem (64 rows)
#define SA_PITCH 72       // halfs per A row in smem
#define A_STAGE_H (TB * SA_PITCH)                 // halfs per A stage (2304)
#define SMEM_LOOP_BYTES ((64*SW_PITCH + 2*3*A_STAGE_H) * 2)   // 126,976 B

// ---------------- persistent device scratch ----------------
__device__ __align__(16) __half g_Xa[(size_t)MX * KX];
__device__ __align__(16) float  g_preX[(size_t)MX * H];
__device__ __align__(16) __half g_Wia[(size_t)H * KX];
__device__ __align__(16) __half g_Wa[(size_t)NTOT * KAUG];
__device__ __align__(16) __half g_Aa[BATCH * KAUG];          // split h: [hi | lo | hi]
__device__ __align__(16) float g_h[BATCH * H];
__device__ __align__(16) float g_P[2 * KCHUNK * TB * NTOT];  // per-team split-K partials
__device__ float g_bsum[H];

// per-team grid barrier state
__device__ volatile unsigned g_gen2[2];
__device__ unsigned g_cnt2[2];

// ---------------- helpers ----------------
__device__ __forceinline__ void split2(float v, __half& hi, __half& lo) {
    hi = __float2half_rn(v);
    lo = __float2half_rn(v - __half2float(hi));
}

__device__ __forceinline__ float tanh_acc(float x) {
    float ax = fabsf(x);
    if (ax > 9.1f) return copysignf(1.0f, x);
    float y = 2.0f * ax * 1.4426950408889634f;
    float n = rintf(y);
    float f = y - n;
    const float c1 = 0.6931471805599453f, c2 = 0.2402265069591007f,
                c3 = 0.05550410866482158f, c4 = 0.009618129107628477f,
                c5 = 0.0013333558146428443f, c6 = 0.00015403530393381609f;
    float p = c6;
    p = fmaf(p, f, c5); p = fmaf(p, f, c4); p = fmaf(p, f, c3);
    p = fmaf(p, f, c2); p = fmaf(p, f, c1); p = fmaf(p, f, 1.0f);
    float e = ldexpf(p, (int)n);
    float r = 1.0f - 2.0f / (e + 1.0f);
    return copysignf(r, x);
}

__device__ __forceinline__ void mma16816(float c[4],
        uint32_t a0, uint32_t a1, uint32_t a2, uint32_t a3,
        uint32_t b0, uint32_t b1) {
    asm volatile(
        "mma.sync.aligned.m16n8k16.row.col.f32.f16.f16.f32 "
        "{%0,%1,%2,%3}, {%4,%5,%6,%7}, {%8,%9}, {%0,%1,%2,%3};\n"
        : "+f"(c[0]), "+f"(c[1]), "+f"(c[2]), "+f"(c[3])
        : "r"(a0), "r"(a1), "r"(a2), "r"(a3), "r"(b0), "r"(b1));
}

__device__ __forceinline__ void ldsm_x4(uint32_t& r0, uint32_t& r1,
                                        uint32_t& r2, uint32_t& r3, uint32_t addr) {
    asm volatile("ldmatrix.sync.aligned.m8n8.x4.shared.b16 {%0,%1,%2,%3}, [%4];"
                 : "=r"(r0), "=r"(r1), "=r"(r2), "=r"(r3) : "r"(addr));
}

__device__ __forceinline__ void cp_async16(void* dst_smem, const void* src) {
    unsigned d = (unsigned)__cvta_generic_to_shared(dst_smem);
    asm volatile("cp.async.ca.shared.global [%0], [%1], 16;\n" :: "r"(d), "l"(src));
}
#define CP_COMMIT() asm volatile("cp.async.commit_group;\n" ::: "memory")
#define CP_WAIT(n)  asm volatile("cp.async.wait_group %0;\n" :: "n"(n) : "memory")

// team-scoped named barrier (256 threads per team)
__device__ __forceinline__ void barT(int team) {
    asm volatile("bar.sync %0, 256;" :: "r"(team + 1) : "memory");
}

// per-team grid barrier across all NCTA CTAs
__device__ __forceinline__ void gbar_team(int team, int ttid) {
    barT(team);
    if (ttid == 0) {
        __threadfence();
        unsigned gen = g_gen2[team];
        unsigned old = atomicAdd(&g_cnt2[team], 1);
        if (old == NCTA - 1) {
            g_cnt2[team] = 0;
            __threadfence();
            g_gen2[team] = gen + 1;
        } else {
            while (g_gen2[team] == gen) { }
            __threadfence();
        }
    }
    barT(team);
}

// ---------------- merged prep kernel ----------------
__global__ void k_prep(const float* __restrict__ x,
                       const float* __restrict__ W_ih,
                       const float* __restrict__ b_ih,
                       const float* __restrict__ b_hh,
                       const float* __restrict__ W_hh,
                       const float* __restrict__ W_ho,
                       const float* __restrict__ B_param,
                       const float* __restrict__ M_hat,
                       const float* __restrict__ B_mask) {
    const int gt = blockIdx.x * blockDim.x + threadIdx.x;
    const int stride = gridDim.x * blockDim.x;

    for (int idx = gt; idx < BATCH * KAUG; idx += stride) g_Aa[idx] = __float2half(0.0f);
    for (int idx = gt; idx < BATCH * H; idx += stride) g_h[idx] = 0.0f;
    for (int idx = gt; idx < H; idx += stride) g_bsum[idx] = b_ih[idx] + b_hh[idx];

    for (int idx = gt; idx < NTOT * H; idx += stride) {
        int r = idx / H, c = idx % H;
        float v;
        if (r < H) {
            v = W_hh[r * H + c];
        } else if (r < 2 * H) {
            int i = r - H, j = c;
            float bij = B_param[i * H + j] * B_mask[i * H + j];
            float bji = B_param[j * H + i] * B_mask[j * H + i];
            v = bij - M_hat[i * H + i] * bji / M_hat[j * H + j];
        } else {
            v = W_ho[(r - 2 * H) * H + c];
        }
        __half hi, lo; split2(v, hi, lo);
        size_t base = (size_t)r * KAUG;
        g_Wa[base + c] = hi;
        g_Wa[base + H + c] = hi;
        g_Wa[base + 2 * H + c] = lo;
    }

    for (int idx = gt; idx < H * I_DIM; idx += stride) {
        int n = idx / I_DIM, k = idx % I_DIM;
        __half hi, lo; split2(W_ih[n * I_DIM + k], hi, lo);
        size_t base = (size_t)n * KX;
        g_Wia[base + k] = hi;
        g_Wia[base + I_DIM + k] = hi;
        g_Wia[base + 2 * I_DIM + k] = lo;
    }

    for (int idx = gt; idx < BATCH * T_STEPS * I_DIM; idx += stride) {
        int b = idx / (T_STEPS * I_DIM);
        int t = (idx / I_DIM) % T_STEPS;
        int k = idx % I_DIM;
        __half hi, lo; split2(x[idx], hi, lo);
        size_t base = ((size_t)t * BATCH + b) * KX;
        g_Xa[base + k] = hi;
        g_Xa[base + I_DIM + k] = lo;
        g_Xa[base + 2 * I_DIM + k] = hi;
    }
}

// ---------------- preX GEMM: preX[32768,1024] = Xa @ Wia^T + bsum ----------------
__global__ void __launch_bounds__(256) k_prex_gemm() {
    __shared__ __align__(16) __half sA[128][40];
    __shared__ __align__(16) __half sB[128][40];
    const int ntile = blockIdx.x, mtile = blockIdx.y;
    const int tid = threadIdx.x;
    const int wid = tid >> 5, lane = tid & 31;
    const int g = lane >> 2, tg = lane & 3;
    const int wm = wid >> 2, wn = wid & 3;

    float c[4][4][4];
#pragma unroll
    for (int a = 0; a < 4; a++)
#pragma unroll
        for (int bq = 0; bq < 4; bq++)
#pragma unroll
            for (int q = 0; q < 4; q++) c[a][bq][q] = 0.0f;

    const uint32_t* Au = (const uint32_t*)g_Xa;
    const uint32_t* Bu = (const uint32_t*)g_Wia;
    uint32_t* sAu = (uint32_t*)&sA[0][0];
    uint32_t* sBu = (uint32_t*)&sB[0][0];

    for (int slab = 0; slab < 24; ++slab) {
        for (int i = tid; i < 128 * 16; i += 256) {
            int row = i >> 4, p = i & 15;
            sAu[row * 20 + p] = Au[(size_t)(mtile * 128 + row) * 384 + slab * 16 + p];
        }
        for (int i = tid; i < 128 * 16; i += 256) {
            int row = i >> 4, p = i & 15;
            sBu[row * 20 + p] = Bu[(size_t)(ntile * 128 + row) * 384 + slab * 16 + p];
        }
        __syncthreads();
#pragma unroll
        for (int kc = 0; kc < 2; ++kc) {
            int kb = kc * 16;
            uint32_t a[4][4], bfrag[4][2];
#pragma unroll
            for (int mf = 0; mf < 4; ++mf) {
                int m0 = wm * 64 + mf * 16;
                a[mf][0] = *(const uint32_t*)&sA[m0 + g][kb + 2 * tg];
                a[mf][1] = *(const uint32_t*)&sA[m0 + g + 8][kb + 2 * tg];
                a[mf][2] = *(const uint32_t*)&sA[m0 + g][kb + 2 * tg + 8];
                a[mf][3] = *(const uint32_t*)&sA[m0 + g + 8][kb + 2 * tg + 8];
            }
#pragma unroll
            for (int nf = 0; nf < 4; ++nf) {
                int n0 = wn * 32 + nf * 8;
                bfrag[nf][0] = *(const uint32_t*)&sB[n0 + g][kb + 2 * tg];
                bfrag[nf][1] = *(const uint32_t*)&sB[n0 + g][kb + 2 * tg + 8];
            }
#pragma unroll
            for (int mf = 0; mf < 4; ++mf)
#pragma unroll
                for (int nf = 0; nf < 4; ++nf)
                    mma16816(c[mf][nf], a[mf][0], a[mf][1], a[mf][2], a[mf][3],
                             bfrag[nf][0], bfrag[nf][1]);
        }
        __syncthreads();
    }
#pragma unroll
    for (int mf = 0; mf < 4; ++mf) {
        int r0 = mtile * 128 + wm * 64 + mf * 16 + g;
#pragma unroll
        for (int nf = 0; nf < 4; ++nf) {
            int col = ntile * 128 + wn * 32 + nf * 8 + 2 * tg;
            float bs0 = g_bsum[col], bs1 = g_bsum[col + 1];
            g_preX[(size_t)r0 * H + col]           = c[mf][nf][0] + bs0;
            g_preX[(size_t)r0 * H + col + 1]       = c[mf][nf][1] + bs1;
            g_preX[(size_t)(r0 + 8) * H + col]     = c[mf][nf][2] + bs0;
            g_preX[(size_t)(r0 + 8) * H + col + 1] = c[mf][nf][3] + bs1;
        }
    }
}

// ---------------- persistent recurrent loop: 2 independent batch-teams per CTA ----------------
// 136 CTAs x 512 threads. Team t (256 thr) handles batches [t*32, t*32+32) with its own
// grid-barrier domain and split-K partials; both teams share the CTA's weight tile.
__global__ void __launch_bounds__(NTHR) k_loop(const float* __restrict__ b_o,
                                               float* __restrict__ out) {
    extern __shared__ __align__(16) __half smem[];
    __half* sWh = smem;                               // 64 x SW_PITCH
    __half* sA0 = smem + 64 * SW_PITCH;               // 2 teams x 3 stages x TB x SA_PITCH

    const int cta = blockIdx.x;
    const int ntile = cta % NTILES;
    const int kch   = cta / NTILES;
    const int tid = threadIdx.x;
    const int team = tid >> 8;                        // 0/1
    const int ttid = tid & 255;
    const int wid = ttid >> 5, lane = tid & 31;       // team-local warp 0..7
    const int g = lane >> 2, tg = lane & 3;
    const int wm = wid >> 2, wn = wid & 3;            // 2(M) x 4(N) warps, 16x16 tiles
    const int ut = cta * 256 + ttid;                  // team-global thread index

    const uint4* A4 = (const uint4*)g_Aa;             // row pitch 384 uint4
    const uint4* B4 = (const uint4*)g_Wa;
    const int kofs4 = kch * 96;
    float* Pmine = g_P + ((size_t)team * KCHUNK + kch) * (TB * NTOT);
    const float* Pteam = g_P + (size_t)team * KCHUNK * (TB * NTOT);
    __half* sAteam = sA0 + team * (3 * A_STAGE_H);

    // ---- load W tile into smem ONCE (64 rows x 768 halfs), all 512 threads ----
    for (int i = tid; i < 64 * 96; i += NTHR) {
        int row = i / 96, q = i % 96;
        *(uint4*)&sWh[row * SW_PITCH + q * 8] =
            B4[(size_t)(ntile * 64 + row) * 384 + kofs4 + q];
    }
    __syncthreads();

    // ldmatrix per-lane addressing
    const uint32_t sWaddr = (uint32_t)__cvta_generic_to_shared(sWh);
    const uint32_t sAaddr = (uint32_t)__cvta_generic_to_shared(sAteam);
    const int a_row = lane & 15;
    const int a_col = (lane >> 4) * 8;
    const int b_row = ((lane >> 4) * 8) + (lane & 7);
    const int b_col = ((lane >> 3) & 1) * 8;
    const int n0 = wn * 16;
    const uint32_t bBase = sWaddr + ((n0 + b_row) * SW_PITCH + b_col) * 2;
    const int m0 = wm * 16;

    // per-thread A-slab element: 256 chunks (32 rows x 8), one per thread
    const int arow = ttid >> 3;
    const int aq   = ttid & 7;
    const int abatch = team * TB;                     // global batch row base

    for (int s = 0; s <= T_STEPS; ++s) {
        // prefetch this team's preX slice into L2
        if (s < T_STEPS && ut < 1024) {
            const float* p = g_preX + ((size_t)s * BATCH + abatch) * H + ut * 32;
            asm volatile("prefetch.global.L2 [%0];" :: "l"(p));
        }

        // prologue: issue A slabs 0,1 (1 chunk/thread each)
#pragma unroll
        for (int pf = 0; pf < 2; ++pf) {
            __half* dst = sAteam + pf * A_STAGE_H + arow * SA_PITCH + aq * 8;
            cp_async16(dst, A4 + (size_t)(abatch + arow) * 384 + kofs4 + pf * 8 + aq);
            CP_COMMIT();
        }

        float c[2][4];
#pragma unroll
        for (int bq = 0; bq < 2; bq++)
#pragma unroll
            for (int q = 0; q < 4; q++) c[bq][q] = 0.0f;

#pragma unroll 1
        for (int slab = 0; slab < 12; ++slab) {
            if (slab == 11) { CP_WAIT(0); } else { CP_WAIT(1); }
            barT(team);
            if (slab + 2 < 12) {
                int st = (slab + 2) % 3;
                __half* dst = sAteam + st * A_STAGE_H + arow * SA_PITCH + aq * 8;
                cp_async16(dst, A4 + (size_t)(abatch + arow) * 384 + kofs4 + (slab + 2) * 8 + aq);
                CP_COMMIT();
            }
            const uint32_t aStage = sAaddr + (slab % 3) * (A_STAGE_H * 2);
            const int wofs = slab * 64;
#pragma unroll
            for (int kc = 0; kc < 4; ++kc) {
                const int kb = kc * 16;
                uint32_t a[4], bfrag[2][2];
                {
                    uint32_t addr = bBase + (wofs + kb) * 2;
                    ldsm_x4(bfrag[0][0], bfrag[0][1], bfrag[1][0], bfrag[1][1], addr);
                }
                {
                    uint32_t addr = aStage + ((m0 + a_row) * SA_PITCH + kb + a_col) * 2;
                    ldsm_x4(a[0], a[1], a[2], a[3], addr);
                }
#pragma unroll
                for (int nf = 0; nf < 2; ++nf)
                    mma16816(c[nf], a[0], a[1], a[2], a[3], bfrag[nf][0], bfrag[nf][1]);
            }
        }

        // write split-K partials (rows = team-local batch 0..31)
        {
            int r0 = m0 + g;
#pragma unroll
            for (int nf = 0; nf < 2; ++nf) {
                int col = ntile * 64 + wn * 16 + nf * 8 + 2 * tg;
                Pmine[r0 * NTOT + col]           = c[nf][0];
                Pmine[r0 * NTOT + col + 1]       = c[nf][1];
                Pmine[(r0 + 8) * NTOT + col]     = c[nf][2];
                Pmine[(r0 + 8) * NTOT + col + 1] = c[nf][3];
            }
        }

        gbar_team(team, ttid);

        // ---- update phase (team-local, vectorized) ----
        if (s < T_STEPS && ut < TB * H / 4) {
            int b = ut >> 8, nv = (ut & 255) * 4;     // team-local batch, col
            int B = abatch + b;
            float4 pre = *(const float4*)&g_preX[((size_t)s * BATCH + B) * H + nv];
            float4 hl = make_float4(0.f, 0.f, 0.f, 0.f);
#pragma unroll
            for (int k = 0; k < KCHUNK; ++k) {
                const float* P = Pteam + (size_t)k * (TB * NTOT) + (size_t)b * NTOT;
                float4 p1 = *(const float4*)&P[nv];
                float4 p2 = *(const float4*)&P[H + nv];
                pre.x += p1.x; pre.y += p1.y; pre.z += p1.z; pre.w += p1.w;
                hl.x += p2.x; hl.y += p2.y; hl.z += p2.z; hl.w += p2.w;
            }
            float4 hv = *(const float4*)&g_h[B * H + nv];
            float4 hn;
            hn.x = fmaf(ALPHA, tanh_acc(pre.x) - hv.x + hl.x, hv.x);
            hn.y = fmaf(ALPHA, tanh_acc(pre.y) - hv.y + hl.y, hv.y);
            hn.z = fmaf(ALPHA, tanh_acc(pre.z) - hv.z + hl.z, hv.z);
            hn.w = fmaf(ALPHA, tanh_acc(pre.w) - hv.w + hl.w, hv.w);
            *(float4*)&g_h[B * H + nv] = hn;
            __half hix, lox, hiy, loy, hiz, loz, hiw, low;
            split2(hn.x, hix, lox); split2(hn.y, hiy, loy);
            split2(hn.z, hiz, loz); split2(hn.w, hiw, low);
            size_t base = (size_t)B * KAUG;
            __half2 hi01 = __halves2half2(hix, hiy), hi23 = __halves2half2(hiz, hiw);
            __half2 lo01 = __halves2half2(lox, loy), lo23 = __halves2half2(loz, low);
            *(__half2*)&g_Aa[base + nv]         = hi01;
            *(__half2*)&g_Aa[base + nv + 2]     = hi23;
            *(__half2*)&g_Aa[base + H + nv]     = lo01;
            *(__half2*)&g_Aa[base + H + nv + 2] = lo23;
            *(__half2*)&g_Aa[base + 2 * H + nv]     = hi01;
            *(__half2*)&g_Aa[base + 2 * H + nv + 2] = hi23;
        }
        {
            int v = ut - TB * H / 4;
            if (s >= 1 && v >= 0 && v < TB * O_DIM / 4) {
                int b = v >> 5, ov = (v & 31) * 4;
                int B = abatch + b;
                float4 yv = *(const float4*)&b_o[ov];
#pragma unroll
                for (int k = 0; k < KCHUNK; ++k) {
                    const float* P = Pteam + (size_t)k * (TB * NTOT) + (size_t)b * NTOT + 2 * H;
                    float4 p = *(const float4*)&P[ov];
                    yv.x += p.x; yv.y += p.y; yv.z += p.z; yv.w += p.w;
                }
                *(float4*)&out[((size_t)B * T_STEPS + (s - 1)) * O_DIM + ov] = yv;
            }
        }

        gbar_team(team, ttid);
    }
}

// ---------------- launch ----------------
extern "C" void kernel_launch(void* const* d_in, const int* in_sizes, int n_in,
                              void* d_out, int out_size) {
    const float* x       = (const float*)d_in[0];
    const float* W_ih    = (const float*)d_in[1];
    const float* b_ih    = (const float*)d_in[2];
    const float* W_hh    = (const float*)d_in[3];
    const float* b_hh    = (const float*)d_in[4];
    const float* W_ho    = (const float*)d_in[5];
    const float* b_o     = (const float*)d_in[6];
    const float* B_param = (const float*)d_in[7];
    const float* M_hat   = (const float*)d_in[8];
    const float* B_mask  = (const float*)d_in[9];
    float* out = (float*)d_out;

    static int smem_set = 0;
    if (!smem_set) {
        cudaFuncSetAttribute(k_loop, cudaFuncAttributeMaxDynamicSharedMemorySize,
                             SMEM_LOOP_BYTES);
        smem_set = 1;
    }

    k_prep<<<512, 256>>>(x, W_ih, b_ih, b_hh, W_hh, W_ho, B_param, M_hat, B_mask);
    k_prex_gemm<<<dim3(8, 256), 256>>>();
    k_loop<<<NCTA, NTHR, SMEM_LOOP_BYTES>>>(b_o, out);
}

// round 11
// speedup vs baseline: 1.1474x; 1.1474x over previous
#include <cuda_runtime.h>
#include <cuda_fp16.h>
#include <stdint.h>

#define H       1024
#define I_DIM   256
#define O_DIM   128
#define BATCH   64
#define T_STEPS 512
#define NTOT    2176      // H + H + O
#define KAUG    3072      // 3*H
#define KX      768       // 3*I
#define MX      32768     // BATCH*T
#define ALPHA   0.1f

#define NTILES  34        // 2176/64
#define KCHUNK  4         // K split: 4 x 768
#define NCTA    136       // NTILES*KCHUNK
#define NTHR    256
#define NT_ALL  (NCTA*NTHR)

#define SW_PITCH 776      // halfs per W row in smem (64 rows), 1552B
#define SA_PITCH 136      // halfs per A row in smem (128-wide slab + 8 pad), 272B
#define NSLAB    6        // 6 slabs of 128 halfs = K 768
#define A_STAGE_H (64 * SA_PITCH)
#define SMEM_LOOP_BYTES ((64*SW_PITCH + 3*A_STAGE_H) * 2)   // 151,552 B

// ---------------- persistent device scratch ----------------
__device__ __align__(16) __half g_Xa[(size_t)MX * KX];
__device__ __align__(16) float  g_preX[(size_t)MX * H];
__device__ __align__(16) __half g_Wia[(size_t)H * KX];
__device__ __align__(16) __half g_Wa[(size_t)NTOT * KAUG];
__device__ __align__(16) __half g_Aa[BATCH * KAUG];          // split h: [hi | lo | hi]
__device__ __align__(16) float g_h[BATCH * H];
__device__ __align__(16) float g_P4[KCHUNK * BATCH * NTOT];
__device__ float g_bsum[H];

__device__ volatile unsigned g_gen;
__device__ unsigned g_cnt;

// ---------------- helpers ----------------
__device__ __forceinline__ void split2(float v, __half& hi, __half& lo) {
    hi = __float2half_rn(v);
    lo = __float2half_rn(v - __half2float(hi));
}

__device__ __forceinline__ float tanh_acc(float x) {
    float ax = fabsf(x);
    if (ax > 9.1f) return copysignf(1.0f, x);
    float y = 2.0f * ax * 1.4426950408889634f;
    float n = rintf(y);
    float f = y - n;
    const float c1 = 0.6931471805599453f, c2 = 0.2402265069591007f,
                c3 = 0.05550410866482158f, c4 = 0.009618129107628477f,
                c5 = 0.0013333558146428443f, c6 = 0.00015403530393381609f;
    float p = c6;
    p = fmaf(p, f, c5); p = fmaf(p, f, c4); p = fmaf(p, f, c3);
    p = fmaf(p, f, c2); p = fmaf(p, f, c1); p = fmaf(p, f, 1.0f);
    float e = ldexpf(p, (int)n);
    float r = 1.0f - 2.0f / (e + 1.0f);
    return copysignf(r, x);
}

__device__ __forceinline__ void mma16816(float c[4],
        uint32_t a0, uint32_t a1, uint32_t a2, uint32_t a3,
        uint32_t b0, uint32_t b1) {
    asm volatile(
        "mma.sync.aligned.m16n8k16.row.col.f32.f16.f16.f32 "
        "{%0,%1,%2,%3}, {%4,%5,%6,%7}, {%8,%9}, {%0,%1,%2,%3};\n"
        : "+f"(c[0]), "+f"(c[1]), "+f"(c[2]), "+f"(c[3])
        : "r"(a0), "r"(a1), "r"(a2), "r"(a3), "r"(b0), "r"(b1));
}

__device__ __forceinline__ void ldsm_x4(uint32_t& r0, uint32_t& r1,
                                        uint32_t& r2, uint32_t& r3, uint32_t addr) {
    asm volatile("ldmatrix.sync.aligned.m8n8.x4.shared.b16 {%0,%1,%2,%3}, [%4];"
                 : "=r"(r0), "=r"(r1), "=r"(r2), "=r"(r3) : "r"(addr));
}

__device__ __forceinline__ void cp_async16(void* dst_smem, const void* src) {
    unsigned d = (unsigned)__cvta_generic_to_shared(dst_smem);
    asm volatile("cp.async.ca.shared.global [%0], [%1], 16;\n" :: "r"(d), "l"(src));
}
#define CP_COMMIT() asm volatile("cp.async.commit_group;\n" ::: "memory")
#define CP_WAIT(n)  asm volatile("cp.async.wait_group %0;\n" :: "n"(n) : "memory")

__device__ __forceinline__ void gbar() {
    __syncthreads();
    if (threadIdx.x == 0) {
        __threadfence();
        unsigned gen = g_gen;
        unsigned old = atomicAdd(&g_cnt, 1);
        if (old == NCTA - 1) {
            g_cnt = 0;
            __threadfence();
            g_gen = gen + 1;
        } else {
            while (g_gen == gen) { }
            __threadfence();
        }
    }
    __syncthreads();
}

// ---------------- merged prep kernel ----------------
__global__ void k_prep(const float* __restrict__ x,
                       const float* __restrict__ W_ih,
                       const float* __restrict__ b_ih,
                       const float* __restrict__ b_hh,
                       const float* __restrict__ W_hh,
                       const float* __restrict__ W_ho,
                       const float* __restrict__ B_param,
                       const float* __restrict__ M_hat,
                       const float* __restrict__ B_mask) {
    const int gt = blockIdx.x * blockDim.x + threadIdx.x;
    const int stride = gridDim.x * blockDim.x;

    for (int idx = gt; idx < BATCH * KAUG; idx += stride) g_Aa[idx] = __float2half(0.0f);
    for (int idx = gt; idx < BATCH * H; idx += stride) g_h[idx] = 0.0f;
    for (int idx = gt; idx < H; idx += stride) g_bsum[idx] = b_ih[idx] + b_hh[idx];

    for (int idx = gt; idx < NTOT * H; idx += stride) {
        int r = idx / H, c = idx % H;
        float v;
        if (r < H) {
            v = W_hh[r * H + c];
        } else if (r < 2 * H) {
            int i = r - H, j = c;
            float bij = B_param[i * H + j] * B_mask[i * H + j];
            float bji = B_param[j * H + i] * B_mask[j * H + i];
            v = bij - M_hat[i * H + i] * bji / M_hat[j * H + j];
        } else {
            v = W_ho[(r - 2 * H) * H + c];
        }
        __half hi, lo; split2(v, hi, lo);
        size_t base = (size_t)r * KAUG;
        g_Wa[base + c] = hi;
        g_Wa[base + H + c] = hi;
        g_Wa[base + 2 * H + c] = lo;
    }

    for (int idx = gt; idx < H * I_DIM; idx += stride) {
        int n = idx / I_DIM, k = idx % I_DIM;
        __half hi, lo; split2(W_ih[n * I_DIM + k], hi, lo);
        size_t base = (size_t)n * KX;
        g_Wia[base + k] = hi;
        g_Wia[base + I_DIM + k] = hi;
        g_Wia[base + 2 * I_DIM + k] = lo;
    }

    for (int idx = gt; idx < BATCH * T_STEPS * I_DIM; idx += stride) {
        int b = idx / (T_STEPS * I_DIM);
        int t = (idx / I_DIM) % T_STEPS;
        int k = idx % I_DIM;
        __half hi, lo; split2(x[idx], hi, lo);
        size_t base = ((size_t)t * BATCH + b) * KX;
        g_Xa[base + k] = hi;
        g_Xa[base + I_DIM + k] = lo;
        g_Xa[base + 2 * I_DIM + k] = hi;
    }
}

// ---------------- preX GEMM: preX[32768,1024] = Xa @ Wia^T + bsum ----------------
__global__ void __launch_bounds__(256) k_prex_gemm() {
    __shared__ __align__(16) __half sA[128][40];
    __shared__ __align__(16) __half sB[128][40];
    const int ntile = blockIdx.x, mtile = blockIdx.y;
    const int tid = threadIdx.x;
    const int wid = tid >> 5, lane = tid & 31;
    const int g = lane >> 2, tg = lane & 3;
    const int wm = wid >> 2, wn = wid & 3;

    float c[4][4][4];
#pragma unroll
    for (int a = 0; a < 4; a++)
#pragma unroll
        for (int bq = 0; bq < 4; bq++)
#pragma unroll
            for (int q = 0; q < 4; q++) c[a][bq][q] = 0.0f;

    const uint32_t* Au = (const uint32_t*)g_Xa;
    const uint32_t* Bu = (const uint32_t*)g_Wia;
    uint32_t* sAu = (uint32_t*)&sA[0][0];
    uint32_t* sBu = (uint32_t*)&sB[0][0];

    for (int slab = 0; slab < 24; ++slab) {
        for (int i = tid; i < 128 * 16; i += 256) {
            int row = i >> 4, p = i & 15;
            sAu[row * 20 + p] = Au[(size_t)(mtile * 128 + row) * 384 + slab * 16 + p];
        }
        for (int i = tid; i < 128 * 16; i += 256) {
            int row = i >> 4, p = i & 15;
            sBu[row * 20 + p] = Bu[(size_t)(ntile * 128 + row) * 384 + slab * 16 + p];
        }
        __syncthreads();
#pragma unroll
        for (int kc = 0; kc < 2; ++kc) {
            int kb = kc * 16;
            uint32_t a[4][4], bfrag[4][2];
#pragma unroll
            for (int mf = 0; mf < 4; ++mf) {
                int m0 = wm * 64 + mf * 16;
                a[mf][0] = *(const uint32_t*)&sA[m0 + g][kb + 2 * tg];
                a[mf][1] = *(const uint32_t*)&sA[m0 + g + 8][kb + 2 * tg];
                a[mf][2] = *(const uint32_t*)&sA[m0 + g][kb + 2 * tg + 8];
                a[mf][3] = *(const uint32_t*)&sA[m0 + g + 8][kb + 2 * tg + 8];
            }
#pragma unroll
            for (int nf = 0; nf < 4; ++nf) {
                int n0 = wn * 32 + nf * 8;
                bfrag[nf][0] = *(const uint32_t*)&sB[n0 + g][kb + 2 * tg];
                bfrag[nf][1] = *(const uint32_t*)&sB[n0 + g][kb + 2 * tg + 8];
            }
#pragma unroll
            for (int mf = 0; mf < 4; ++mf)
#pragma unroll
                for (int nf = 0; nf < 4; ++nf)
                    mma16816(c[mf][nf], a[mf][0], a[mf][1], a[mf][2], a[mf][3],
                             bfrag[nf][0], bfrag[nf][1]);
        }
        __syncthreads();
    }
#pragma unroll
    for (int mf = 0; mf < 4; ++mf) {
        int r0 = mtile * 128 + wm * 64 + mf * 16 + g;
#pragma unroll
        for (int nf = 0; nf < 4; ++nf) {
            int col = ntile * 128 + wn * 32 + nf * 8 + 2 * tg;
            float bs0 = g_bsum[col], bs1 = g_bsum[col + 1];
            g_preX[(size_t)r0 * H + col]           = c[mf][nf][0] + bs0;
            g_preX[(size_t)r0 * H + col + 1]       = c[mf][nf][1] + bs1;
            g_preX[(size_t)(r0 + 8) * H + col]     = c[mf][nf][2] + bs0;
            g_preX[(size_t)(r0 + 8) * H + col + 1] = c[mf][nf][3] + bs1;
        }
    }
}

// ---------------- persistent recurrent loop (weight-stationary, wide slabs) ----------------
__global__ void __launch_bounds__(NTHR) k_loop(const float* __restrict__ b_o,
                                               float* __restrict__ out) {
    extern __shared__ __align__(16) __half smem[];
    __half* sWh = smem;                              // 64 x SW_PITCH
    __half* sAh = smem + 64 * SW_PITCH;              // 3 stages x 64 x SA_PITCH

    const int cta = blockIdx.x;
    const int ntile = cta % NTILES;
    const int kch   = cta / NTILES;
    const int tid = threadIdx.x;
    const int wid = tid >> 5, lane = tid & 31;
    const int g = lane >> 2, tg = lane & 3;
    const int wm = wid >> 2, wn = wid & 3;           // 2(M) x 4(N) warps, 32x16 tiles
    const int gt = cta * NTHR + tid;

    const uint4* A4 = (const uint4*)g_Aa;            // row pitch 384 uint4
    const uint4* B4 = (const uint4*)g_Wa;
    const int kofs4 = kch * 96;
    float* Pmine = g_P4 + kch * (BATCH * NTOT);

    // ---- load W tile into smem ONCE (64 rows x 768 halfs) ----
    for (int i = tid; i < 64 * 96; i += NTHR) {
        int row = i / 96, q = i % 96;
        *(uint4*)&sWh[row * SW_PITCH + q * 8] =
            B4[(size_t)(ntile * 64 + row) * 384 + kofs4 + q];
    }
    __syncthreads();

    // ldmatrix per-lane addressing (byte offsets within smem)
    const uint32_t sWaddr = (uint32_t)__cvta_generic_to_shared(sWh);
    const uint32_t sAaddr = (uint32_t)__cvta_generic_to_shared(sAh);
    const int a_row = lane & 15;
    const int a_col = (lane >> 4) * 8;
    const int b_row = ((lane >> 4) * 8) + (lane & 7);
    const int b_col = ((lane >> 3) & 1) * 8;
    const int n0 = wn * 16;
    const uint32_t bBase = sWaddr + ((n0 + b_row) * SW_PITCH + b_col) * 2;

    for (int s = 0; s <= T_STEPS; ++s) {
        // prefetch preX row for this step into L2
        if (s < T_STEPS && gt < 2048) {
            const float* p = g_preX + ((size_t)s * BATCH) * H + gt * 32;
            asm volatile("prefetch.global.L2 [%0];" :: "l"(p));
        }

        // prologue: issue A slabs 0,1 (each 64 rows x 128 halfs = 16 uint4/row)
#pragma unroll
        for (int pf = 0; pf < 2; ++pf) {
            for (int e = tid; e < 1024; e += NTHR) {
                int row = e >> 4, q = e & 15;
                __half* dst = sAh + pf * A_STAGE_H + row * SA_PITCH + q * 8;
                cp_async16(dst, A4 + (size_t)row * 384 + kofs4 + pf * 16 + q);
            }
            CP_COMMIT();
        }

        float c[2][2][4];
#pragma unroll
        for (int a = 0; a < 2; a++)
#pragma unroll
            for (int bq = 0; bq < 2; bq++)
#pragma unroll
                for (int q = 0; q < 4; q++) c[a][bq][q] = 0.0f;

#pragma unroll 1
        for (int slab = 0; slab < NSLAB; ++slab) {
            if (slab == NSLAB - 1) { CP_WAIT(0); } else { CP_WAIT(1); }
            __syncthreads();
            if (slab + 2 < NSLAB) {
                int st = (slab + 2) % 3;
                for (int e = tid; e < 1024; e += NTHR) {
                    int row = e >> 4, q = e & 15;
                    __half* dst = sAh + st * A_STAGE_H + row * SA_PITCH + q * 8;
                    cp_async16(dst, A4 + (size_t)row * 384 + kofs4 + (slab + 2) * 16 + q);
                }
                CP_COMMIT();
            }
            const uint32_t aStage = sAaddr + (slab % 3) * (A_STAGE_H * 2);
            const int wofs = slab * 128;
#pragma unroll
            for (int kc = 0; kc < 8; ++kc) {
                const int kb = kc * 16;
                uint32_t a[2][4], bfrag[2][2];
                {   // B: one ldmatrix.x4 covers both n-frags
                    uint32_t addr = bBase + (wofs + kb) * 2;
                    ldsm_x4(bfrag[0][0], bfrag[0][1], bfrag[1][0], bfrag[1][1], addr);
                }
#pragma unroll
                for (int mf = 0; mf < 2; ++mf) {
                    int m0 = wm * 32 + mf * 16;
                    uint32_t addr = aStage + ((m0 + a_row) * SA_PITCH + kb + a_col) * 2;
                    ldsm_x4(a[mf][0], a[mf][1], a[mf][2], a[mf][3], addr);
                }
#pragma unroll
                for (int mf = 0; mf < 2; ++mf)
#pragma unroll
                    for (int nf = 0; nf < 2; ++nf)
                        mma16816(c[mf][nf], a[mf][0], a[mf][1], a[mf][2], a[mf][3],
                                 bfrag[nf][0], bfrag[nf][1]);
            }
        }

        // write split-K partials
#pragma unroll
        for (int mf = 0; mf < 2; ++mf) {
            int r0 = wm * 32 + mf * 16 + g;
#pragma unroll
            for (int nf = 0; nf < 2; ++nf) {
                int col = ntile * 64 + wn * 16 + nf * 8 + 2 * tg;
                Pmine[r0 * NTOT + col]           = c[mf][nf][0];
                Pmine[r0 * NTOT + col + 1]       = c[mf][nf][1];
                Pmine[(r0 + 8) * NTOT + col]     = c[mf][nf][2];
                Pmine[(r0 + 8) * NTOT + col + 1] = c[mf][nf][3];
            }
        }

        gbar();

        // ---- update phase (vectorized float4, one strip per thread) ----
        if (s < T_STEPS && gt < (BATCH * H / 4)) {
            int b = gt >> 8, nv = (gt & 255) * 4;
            float4 pre = *(const float4*)&g_preX[((size_t)s * BATCH + b) * H + nv];
            float4 hl = make_float4(0.f, 0.f, 0.f, 0.f);
#pragma unroll
            for (int k = 0; k < KCHUNK; ++k) {
                const float* P = g_P4 + k * (BATCH * NTOT) + b * NTOT;
                float4 p1 = *(const float4*)&P[nv];
                float4 p2 = *(const float4*)&P[H + nv];
                pre.x += p1.x; pre.y += p1.y; pre.z += p1.z; pre.w += p1.w;
                hl.x += p2.x; hl.y += p2.y; hl.z += p2.z; hl.w += p2.w;
            }
            float4 hv = *(const float4*)&g_h[b * H + nv];
            float4 hn;
            hn.x = fmaf(ALPHA, tanh_acc(pre.x) - hv.x + hl.x, hv.x);
            hn.y = fmaf(ALPHA, tanh_acc(pre.y) - hv.y + hl.y, hv.y);
            hn.z = fmaf(ALPHA, tanh_acc(pre.z) - hv.z + hl.z, hv.z);
            hn.w = fmaf(ALPHA, tanh_acc(pre.w) - hv.w + hl.w, hv.w);
            *(float4*)&g_h[b * H + nv] = hn;
            __half hix, lox, hiy, loy, hiz, loz, hiw, low;
            split2(hn.x, hix, lox); split2(hn.y, hiy, loy);
            split2(hn.z, hiz, loz); split2(hn.w, hiw, low);
            size_t base = (size_t)b * KAUG;
            __half2 hi01 = __halves2half2(hix, hiy), hi23 = __halves2half2(hiz, hiw);
            __half2 lo01 = __halves2half2(lox, loy), lo23 = __halves2half2(loz, low);
            *(__half2*)&g_Aa[base + nv]         = hi01;
            *(__half2*)&g_Aa[base + nv + 2]     = hi23;
            *(__half2*)&g_Aa[base + H + nv]     = lo01;
            *(__half2*)&g_Aa[base + H + nv + 2] = lo23;
            *(__half2*)&g_Aa[base + 2 * H + nv]     = hi01;
            *(__half2*)&g_Aa[base + 2 * H + nv + 2] = hi23;
        }
        {
            int v = gt - (BATCH * H / 4);
            if (s >= 1 && v >= 0 && v < (BATCH * O_DIM / 4)) {
                int b = v >> 5, ov = (v & 31) * 4;
                float4 yv = *(const float4*)&b_o[ov];
#pragma unroll
                for (int k = 0; k < KCHUNK; ++k) {
                    const float* P = g_P4 + k * (BATCH * NTOT) + b * NTOT + 2 * H;
                    float4 p = *(const float4*)&P[ov];
                    yv.x += p.x; yv.y += p.y; yv.z += p.z; yv.w += p.w;
                }
                *(float4*)&out[((size_t)b * T_STEPS + (s - 1)) * O_DIM + ov] = yv;
            }
        }

        gbar();
    }
}

// ---------------- launch ----------------
extern "C" void kernel_launch(void* const* d_in, const int* in_sizes, int n_in,
                              void* d_out, int out_size) {
    const float* x       = (const float*)d_in[0];
    const float* W_ih    = (const float*)d_in[1];
    const float* b_ih    = (const float*)d_in[2];
    const float* W_hh    = (const float*)d_in[3];
    const float* b_hh    = (const float*)d_in[4];
    const float* W_ho    = (const float*)d_in[5];
    const float* b_o     = (const float*)d_in[6];
    const float* B_param = (const float*)d_in[7];
    const float* M_hat   = (const float*)d_in[8];
    const float* B_mask  = (const float*)d_in[9];
    float* out = (float*)d_out;

    static int smem_set = 0;
    if (!smem_set) {
        cudaFuncSetAttribute(k_loop, cudaFuncAttributeMaxDynamicSharedMemorySize,
                             SMEM_LOOP_BYTES);
        smem_set = 1;
    }

    k_prep<<<512, 256>>>(x, W_ih, b_ih, b_hh, W_hh, W_ho, B_param, M_hat, B_mask);
    k_prex_gemm<<<dim3(8, 256), 256>>>();
    k_loop<<<NCTA, NTHR, SMEM_LOOP_BYTES>>>(b_o, out);
}

// round 12
// speedup vs baseline: 1.2364x; 1.0776x over previous
#include <cuda_runtime.h>
#include <cuda_fp16.h>
#include <stdint.h>

#define H       1024
#define I_DIM   256
#define O_DIM   128
#define BATCH   64
#define T_STEPS 512
#define NTOT    2176      // H + H + O
#define KAUG    3072      // 3*H
#define KX      768       // 3*I
#define MX      32768     // BATCH*T
#define ALPHA   0.1f

#define NTILES  34        // 2176/64
#define KCHUNK  4         // K split: 4 x 768
#define NCTA    136       // NTILES*KCHUNK
#define NTHR    256
#define NT_ALL  (NCTA*NTHR)

#define SW_PITCH 776      // halfs per W row in smem (64 rows)
#define SA_PITCH 264      // halfs per A row in smem (256-wide slab + 8 pad)
#define NSLAB    3        // 3 slabs of 256 halfs = K 768
#define A_STAGE_H (64 * SA_PITCH)
#define SMEM_LOOP_BYTES ((64*SW_PITCH + 3*A_STAGE_H) * 2)   // 200,704 B

// ---------------- persistent device scratch ----------------
__device__ __align__(16) __half g_Xa[(size_t)MX * KX];
__device__ __align__(16) float  g_preX[(size_t)MX * H];
__device__ __align__(16) __half g_Wia[(size_t)H * KX];
__device__ __align__(16) __half g_Wa[(size_t)NTOT * KAUG];
__device__ __align__(16) __half g_Aa[BATCH * KAUG];          // split h: [hi | lo | hi]
__device__ __align__(16) float g_h[BATCH * H];
__device__ __align__(16) float g_P4[KCHUNK * BATCH * NTOT];
__device__ float g_bsum[H];

__device__ volatile unsigned g_gen;
__device__ unsigned g_cnt;
__device__ unsigned g_grp[17];     // per-group monotonic arrival counters

// ---------------- helpers ----------------
__device__ __forceinline__ void split2(float v, __half& hi, __half& lo) {
    hi = __float2half_rn(v);
    lo = __float2half_rn(v - __half2float(hi));
}

__device__ __forceinline__ float tanh_acc(float x) {
    float ax = fabsf(x);
    if (ax > 9.1f) return copysignf(1.0f, x);
    float y = 2.0f * ax * 1.4426950408889634f;
    float n = rintf(y);
    float f = y - n;
    const float c1 = 0.6931471805599453f, c2 = 0.2402265069591007f,
                c3 = 0.05550410866482158f, c4 = 0.009618129107628477f,
                c5 = 0.0013333558146428443f, c6 = 0.00015403530393381609f;
    float p = c6;
    p = fmaf(p, f, c5); p = fmaf(p, f, c4); p = fmaf(p, f, c3);
    p = fmaf(p, f, c2); p = fmaf(p, f, c1); p = fmaf(p, f, 1.0f);
    float e = ldexpf(p, (int)n);
    float r = 1.0f - 2.0f / (e + 1.0f);
    return copysignf(r, x);
}

__device__ __forceinline__ void mma16816(float c[4],
        uint32_t a0, uint32_t a1, uint32_t a2, uint32_t a3,
        uint32_t b0, uint32_t b1) {
    asm volatile(
        "mma.sync.aligned.m16n8k16.row.col.f32.f16.f16.f32 "
        "{%0,%1,%2,%3}, {%4,%5,%6,%7}, {%8,%9}, {%0,%1,%2,%3};\n"
        : "+f"(c[0]), "+f"(c[1]), "+f"(c[2]), "+f"(c[3])
        : "r"(a0), "r"(a1), "r"(a2), "r"(a3), "r"(b0), "r"(b1));
}

__device__ __forceinline__ void ldsm_x4(uint32_t& r0, uint32_t& r1,
                                        uint32_t& r2, uint32_t& r3, uint32_t addr) {
    asm volatile("ldmatrix.sync.aligned.m8n8.x4.shared.b16 {%0,%1,%2,%3}, [%4];"
                 : "=r"(r0), "=r"(r1), "=r"(r2), "=r"(r3) : "r"(addr));
}

__device__ __forceinline__ void cp_async16(void* dst_smem, const void* src) {
    unsigned d = (unsigned)__cvta_generic_to_shared(dst_smem);
    asm volatile("cp.async.ca.shared.global [%0], [%1], 16;\n" :: "r"(d), "l"(src));
}
#define CP_COMMIT() asm volatile("cp.async.commit_group;\n" ::: "memory")
#define CP_WAIT(n)  asm volatile("cp.async.wait_group %0;\n" :: "n"(n) : "memory")

__device__ __forceinline__ void gbar() {
    __syncthreads();
    if (threadIdx.x == 0) {
        __threadfence();
        unsigned gen = g_gen;
        unsigned old = atomicAdd(&g_cnt, 1);
        if (old == NCTA - 1) {
            g_cnt = 0;
            __threadfence();
            g_gen = gen + 1;
        } else {
            while (g_gen == gen) { }
            __threadfence();
        }
    }
    __syncthreads();
}

// 8-CTA group sync on a monotonic counter
__device__ __forceinline__ void gsync(int grp, unsigned target) {
    __syncthreads();
    if (threadIdx.x == 0) {
        __threadfence();
        atomicAdd(&g_grp[grp], 1u);
        while (*(volatile unsigned*)&g_grp[grp] < target) { }
        __threadfence();
    }
    __syncthreads();
}

// ---------------- merged prep kernel ----------------
__global__ void k_prep(const float* __restrict__ x,
                       const float* __restrict__ W_ih,
                       const float* __restrict__ b_ih,
                       const float* __restrict__ b_hh,
                       const float* __restrict__ W_hh,
                       const float* __restrict__ W_ho,
                       const float* __restrict__ B_param,
                       const float* __restrict__ M_hat,
                       const float* __restrict__ B_mask) {
    const int gt = blockIdx.x * blockDim.x + threadIdx.x;
    const int stride = gridDim.x * blockDim.x;

    if (gt < 17) g_grp[gt] = 0u;    // reset group counters each launch
    for (int idx = gt; idx < BATCH * KAUG; idx += stride) g_Aa[idx] = __float2half(0.0f);
    for (int idx = gt; idx < BATCH * H; idx += stride) g_h[idx] = 0.0f;
    for (int idx = gt; idx < H; idx += stride) g_bsum[idx] = b_ih[idx] + b_hh[idx];

    for (int idx = gt; idx < NTOT * H; idx += stride) {
        int r = idx / H, c = idx % H;
        float v;
        if (r < H) {
            v = W_hh[r * H + c];
        } else if (r < 2 * H) {
            int i = r - H, j = c;
            float bij = B_param[i * H + j] * B_mask[i * H + j];
            float bji = B_param[j * H + i] * B_mask[j * H + i];
            v = bij - M_hat[i * H + i] * bji / M_hat[j * H + j];
        } else {
            v = W_ho[(r - 2 * H) * H + c];
        }
        __half hi, lo; split2(v, hi, lo);
        size_t base = (size_t)r * KAUG;
        g_Wa[base + c] = hi;
        g_Wa[base + H + c] = hi;
        g_Wa[base + 2 * H + c] = lo;
    }

    for (int idx = gt; idx < H * I_DIM; idx += stride) {
        int n = idx / I_DIM, k = idx % I_DIM;
        __half hi, lo; split2(W_ih[n * I_DIM + k], hi, lo);
        size_t base = (size_t)n * KX;
        g_Wia[base + k] = hi;
        g_Wia[base + I_DIM + k] = hi;
        g_Wia[base + 2 * I_DIM + k] = lo;
    }

    for (int idx = gt; idx < BATCH * T_STEPS * I_DIM; idx += stride) {
        int b = idx / (T_STEPS * I_DIM);
        int t = (idx / I_DIM) % T_STEPS;
        int k = idx % I_DIM;
        __half hi, lo; split2(x[idx], hi, lo);
        size_t base = ((size_t)t * BATCH + b) * KX;
        g_Xa[base + k] = hi;
        g_Xa[base + I_DIM + k] = lo;
        g_Xa[base + 2 * I_DIM + k] = hi;
    }
}

// ---------------- preX GEMM: preX[32768,1024] = Xa @ Wia^T + bsum ----------------
__global__ void __launch_bounds__(256) k_prex_gemm() {
    __shared__ __align__(16) __half sA[128][40];
    __shared__ __align__(16) __half sB[128][40];
    const int ntile = blockIdx.x, mtile = blockIdx.y;
    const int tid = threadIdx.x;
    const int wid = tid >> 5, lane = tid & 31;
    const int g = lane >> 2, tg = lane & 3;
    const int wm = wid >> 2, wn = wid & 3;

    float c[4][4][4];
#pragma unroll
    for (int a = 0; a < 4; a++)
#pragma unroll
        for (int bq = 0; bq < 4; bq++)
#pragma unroll
            for (int q = 0; q < 4; q++) c[a][bq][q] = 0.0f;

    const uint32_t* Au = (const uint32_t*)g_Xa;
    const uint32_t* Bu = (const uint32_t*)g_Wia;
    uint32_t* sAu = (uint32_t*)&sA[0][0];
    uint32_t* sBu = (uint32_t*)&sB[0][0];

    for (int slab = 0; slab < 24; ++slab) {
        for (int i = tid; i < 128 * 16; i += 256) {
            int row = i >> 4, p = i & 15;
            sAu[row * 20 + p] = Au[(size_t)(mtile * 128 + row) * 384 + slab * 16 + p];
        }
        for (int i = tid; i < 128 * 16; i += 256) {
            int row = i >> 4, p = i & 15;
            sBu[row * 20 + p] = Bu[(size_t)(ntile * 128 + row) * 384 + slab * 16 + p];
        }
        __syncthreads();
#pragma unroll
        for (int kc = 0; kc < 2; ++kc) {
            int kb = kc * 16;
            uint32_t a[4][4], bfrag[4][2];
#pragma unroll
            for (int mf = 0; mf < 4; ++mf) {
                int m0 = wm * 64 + mf * 16;
                a[mf][0] = *(const uint32_t*)&sA[m0 + g][kb + 2 * tg];
                a[mf][1] = *(const uint32_t*)&sA[m0 + g + 8][kb + 2 * tg];
                a[mf][2] = *(const uint32_t*)&sA[m0 + g][kb + 2 * tg + 8];
                a[mf][3] = *(const uint32_t*)&sA[m0 + g + 8][kb + 2 * tg + 8];
            }
#pragma unroll
            for (int nf = 0; nf < 4; ++nf) {
                int n0 = wn * 32 + nf * 8;
                bfrag[nf][0] = *(const uint32_t*)&sB[n0 + g][kb + 2 * tg];
                bfrag[nf][1] = *(const uint32_t*)&sB[n0 + g][kb + 2 * tg + 8];
            }
#pragma unroll
            for (int mf = 0; mf < 4; ++mf)
#pragma unroll
                for (int nf = 0; nf < 4; ++nf)
                    mma16816(c[mf][nf], a[mf][0], a[mf][1], a[mf][2], a[mf][3],
                             bfrag[nf][0], bfrag[nf][1]);
        }
        __syncthreads();
    }
#pragma unroll
    for (int mf = 0; mf < 4; ++mf) {
        int r0 = mtile * 128 + wm * 64 + mf * 16 + g;
#pragma unroll
        for (int nf = 0; nf < 4; ++nf) {
            int col = ntile * 128 + wn * 32 + nf * 8 + 2 * tg;
            float bs0 = g_bsum[col], bs1 = g_bsum[col + 1];
            g_preX[(size_t)r0 * H + col]           = c[mf][nf][0] + bs0;
            g_preX[(size_t)r0 * H + col + 1]       = c[mf][nf][1] + bs1;
            g_preX[(size_t)(r0 + 8) * H + col]     = c[mf][nf][2] + bs0;
            g_preX[(size_t)(r0 + 8) * H + col + 1] = c[mf][nf][3] + bs1;
        }
    }
}

// ---------------- persistent recurrent loop ----------------
// 136 CTAs = 34 ntiles x 4 kchunks. Groups of 8 CTAs own the update of one
// 64-col h range (ntile g + ntile 16+g) or the y output (ntiles 32,33).
__global__ void __launch_bounds__(NTHR) k_loop(const float* __restrict__ b_o,
                                               float* __restrict__ out) {
    extern __shared__ __align__(16) __half smem[];
    __half* sWh = smem;                              // 64 x SW_PITCH
    __half* sAh = smem + 64 * SW_PITCH;              // 3 stages x 64 x SA_PITCH

    const int cta = blockIdx.x;
    const int ntile = cta % NTILES;
    const int kch   = cta / NTILES;
    const int tid = threadIdx.x;
    const int wid = tid >> 5, lane = tid & 31;
    const int g = lane >> 2, tg = lane & 3;
    const int wm = wid >> 2, wn = wid & 3;           // 2(M) x 4(N) warps, 32x16 tiles
    const int gt = cta * NTHR + tid;

    // group identity
    const int grp = (ntile < 32) ? (ntile & 15) : 16;
    const int cig = (ntile < 32) ? (kch * 2 + (ntile >> 4)) : (kch * 2 + (ntile & 1));
    const int glt = cig * NTHR + tid;                // 0..2047 within group

    const uint4* A4 = (const uint4*)g_Aa;            // row pitch 384 uint4
    const uint4* B4 = (const uint4*)g_Wa;
    const int kofs4 = kch * 96;
    float* Pmine = g_P4 + kch * (BATCH * NTOT);

    // ---- load W tile into smem ONCE (64 rows x 768 halfs) ----
    for (int i = tid; i < 64 * 96; i += NTHR) {
        int row = i / 96, q = i % 96;
        *(uint4*)&sWh[row * SW_PITCH + q * 8] =
            B4[(size_t)(ntile * 64 + row) * 384 + kofs4 + q];
    }
    __syncthreads();

    // ldmatrix per-lane addressing
    const uint32_t sWaddr = (uint32_t)__cvta_generic_to_shared(sWh);
    const uint32_t sAaddr = (uint32_t)__cvta_generic_to_shared(sAh);
    const int a_row = lane & 15;
    const int a_col = (lane >> 4) * 8;
    const int b_row = ((lane >> 4) * 8) + (lane & 7);
    const int b_col = ((lane >> 3) & 1) * 8;
    const int n0 = wn * 16;
    const uint32_t bBase = sWaddr + ((n0 + b_row) * SW_PITCH + b_col) * 2;

    for (int s = 0; s <= T_STEPS; ++s) {
        // prefetch preX row for this step into L2
        if (s < T_STEPS && gt < 2048) {
            const float* p = g_preX + ((size_t)s * BATCH) * H + gt * 32;
            asm volatile("prefetch.global.L2 [%0];" :: "l"(p));
        }

        // prologue: issue A slabs 0,1 (each 64 rows x 256 halfs = 32 uint4/row)
#pragma unroll
        for (int pf = 0; pf < 2; ++pf) {
            for (int e = tid; e < 2048; e += NTHR) {
                int row = e >> 5, q = e & 31;
                __half* dst = sAh + pf * A_STAGE_H + row * SA_PITCH + q * 8;
                cp_async16(dst, A4 + (size_t)row * 384 + kofs4 + pf * 32 + q);
            }
            CP_COMMIT();
        }

        float c[2][2][4];
#pragma unroll
        for (int a = 0; a < 2; a++)
#pragma unroll
            for (int bq = 0; bq < 2; bq++)
#pragma unroll
                for (int q = 0; q < 4; q++) c[a][bq][q] = 0.0f;

#pragma unroll 1
        for (int slab = 0; slab < NSLAB; ++slab) {
            if (slab == NSLAB - 1) { CP_WAIT(0); } else { CP_WAIT(1); }
            __syncthreads();
            if (slab + 2 < NSLAB) {
                int st = (slab + 2) % 3;
                for (int e = tid; e < 2048; e += NTHR) {
                    int row = e >> 5, q = e & 31;
                    __half* dst = sAh + st * A_STAGE_H + row * SA_PITCH + q * 8;
                    cp_async16(dst, A4 + (size_t)row * 384 + kofs4 + (slab + 2) * 32 + q);
                }
                CP_COMMIT();
            }
            const uint32_t aStage = sAaddr + (slab % 3) * (A_STAGE_H * 2);
            const int wofs = slab * 256;
#pragma unroll
            for (int kc = 0; kc < 16; ++kc) {
                const int kb = kc * 16;
                uint32_t a[2][4], bfrag[2][2];
                {
                    uint32_t addr = bBase + (wofs + kb) * 2;
                    ldsm_x4(bfrag[0][0], bfrag[0][1], bfrag[1][0], bfrag[1][1], addr);
                }
#pragma unroll
                for (int mf = 0; mf < 2; ++mf) {
                    int m0 = wm * 32 + mf * 16;
                    uint32_t addr = aStage + ((m0 + a_row) * SA_PITCH + kb + a_col) * 2;
                    ldsm_x4(a[mf][0], a[mf][1], a[mf][2], a[mf][3], addr);
                }
#pragma unroll
                for (int mf = 0; mf < 2; ++mf)
#pragma unroll
                    for (int nf = 0; nf < 2; ++nf)
                        mma16816(c[mf][nf], a[mf][0], a[mf][1], a[mf][2], a[mf][3],
                                 bfrag[nf][0], bfrag[nf][1]);
            }
        }

        // write split-K partials
#pragma unroll
        for (int mf = 0; mf < 2; ++mf) {
            int r0 = wm * 32 + mf * 16 + g;
#pragma unroll
            for (int nf = 0; nf < 2; ++nf) {
                int col = ntile * 64 + wn * 16 + nf * 8 + 2 * tg;
                Pmine[r0 * NTOT + col]           = c[mf][nf][0];
                Pmine[r0 * NTOT + col + 1]       = c[mf][nf][1];
                Pmine[(r0 + 8) * NTOT + col]     = c[mf][nf][2];
                Pmine[(r0 + 8) * NTOT + col + 1] = c[mf][nf][3];
            }
        }

        // ---- group sync + group-local update ----
        if (s < T_STEPS || grp == 16) gsync(grp, 8u * (unsigned)(s + 1));

        if (grp < 16) {
            if (s < T_STEPS && glt < 1024) {
                int b = glt >> 4, col = grp * 64 + (glt & 15) * 4;
                float4 pre = *(const float4*)&g_preX[((size_t)s * BATCH + b) * H + col];
                float4 hl = make_float4(0.f, 0.f, 0.f, 0.f);
#pragma unroll
                for (int k = 0; k < KCHUNK; ++k) {
                    const float* P = g_P4 + k * (BATCH * NTOT) + b * NTOT;
                    float4 p1 = *(const float4*)&P[col];
                    float4 p2 = *(const float4*)&P[H + col];
                    pre.x += p1.x; pre.y += p1.y; pre.z += p1.z; pre.w += p1.w;
                    hl.x += p2.x; hl.y += p2.y; hl.z += p2.z; hl.w += p2.w;
                }
                float4 hv = *(const float4*)&g_h[b * H + col];
                float4 hn;
                hn.x = fmaf(ALPHA, tanh_acc(pre.x) - hv.x + hl.x, hv.x);
                hn.y = fmaf(ALPHA, tanh_acc(pre.y) - hv.y + hl.y, hv.y);
                hn.z = fmaf(ALPHA, tanh_acc(pre.z) - hv.z + hl.z, hv.z);
                hn.w = fmaf(ALPHA, tanh_acc(pre.w) - hv.w + hl.w, hv.w);
                *(float4*)&g_h[b * H + col] = hn;
                __half hix, lox, hiy, loy, hiz, loz, hiw, low;
                split2(hn.x, hix, lox); split2(hn.y, hiy, loy);
                split2(hn.z, hiz, loz); split2(hn.w, hiw, low);
                size_t base = (size_t)b * KAUG;
                __half2 hi01 = __halves2half2(hix, hiy), hi23 = __halves2half2(hiz, hiw);
                __half2 lo01 = __halves2half2(lox, loy), lo23 = __halves2half2(loz, low);
                *(__half2*)&g_Aa[base + col]         = hi01;
                *(__half2*)&g_Aa[base + col + 2]     = hi23;
                *(__half2*)&g_Aa[base + H + col]     = lo01;
                *(__half2*)&g_Aa[base + H + col + 2] = lo23;
                *(__half2*)&g_Aa[base + 2 * H + col]     = hi01;
                *(__half2*)&g_Aa[base + 2 * H + col + 2] = hi23;
            }
        } else {
            if (s >= 1) {
                int b = glt >> 5, col = (glt & 31) * 4;
                float4 yv = *(const float4*)&b_o[col];
#pragma unroll
                for (int k = 0; k < KCHUNK; ++k) {
                    const float* P = g_P4 + k * (BATCH * NTOT) + b * NTOT + 2 * H;
                    float4 p = *(const float4*)&P[col];
                    yv.x += p.x; yv.y += p.y; yv.z += p.z; yv.w += p.w;
                }
                *(float4*)&out[((size_t)b * T_STEPS + (s - 1)) * O_DIM + col] = yv;
            }
        }

        gbar();
    }
}

// ---------------- launch ----------------
extern "C" void kernel_launch(void* const* d_in, const int* in_sizes, int n_in,
                              void* d_out, int out_size) {
    const float* x       = (const float*)d_in[0];
    const float* W_ih    = (const float*)d_in[1];
    const float* b_ih    = (const float*)d_in[2];
    const float* W_hh    = (const float*)d_in[3];
    const float* b_hh    = (const float*)d_in[4];
    const float* W_ho    = (const float*)d_in[5];
    const float* b_o     = (const float*)d_in[6];
    const float* B_param = (const float*)d_in[7];
    const float* M_hat   = (const float*)d_in[8];
    const float* B_mask  = (const float*)d_in[9];
    float* out = (float*)d_out;

    static int smem_set = 0;
    if (!smem_set) {
        cudaFuncSetAttribute(k_loop, cudaFuncAttributeMaxDynamicSharedMemorySize,
                             SMEM_LOOP_BYTES);
        smem_set = 1;
    }

    k_prep<<<512, 256>>>(x, W_ih, b_ih, b_hh, W_hh, W_ho, B_param, M_hat, B_mask);
    k_prex_gemm<<<dim3(8, 256), 256>>>();
    k_loop<<<NCTA, NTHR, SMEM_LOOP_BYTES>>>(b_o, out);
}